// round 3
// baseline (speedup 1.0000x reference)
#include <cuda_runtime.h>
#include <math.h>

#define NCTA     1024
#define EPI_BASE (NCTA - 128)

// Scratch (device globals — no allocation allowed).
// g_part per (bc, chunk): [0:8) sumD(local dl), [8:72) sumH, [72:136) sumW,
// [136] sum(x^2), [137] chunk total. Stride 144 floats.
__device__ float g_part[128 * 8 * 144];
__device__ float g_c2m[32 * 64];
__device__ int   g_cnt1;   // zero-initialized; self-resetting each launch
__device__ int   g_cnt2;

__global__ __launch_bounds__(256) void k_fused(const float* __restrict__ x,
                                               const float* __restrict__ gamma,
                                               const float* __restrict__ beta,
                                               const float* __restrict__ core1,
                                               const float* __restrict__ core2,
                                               const float* __restrict__ core3,
                                               float* __restrict__ out) {
    const int bid   = blockIdx.x;       // 0..1023, chunk-major so epilogue CTAs launch last
    const int chunk = bid >> 7;         // 0..7  (d in [chunk*8, chunk*8+8))
    const int bc    = bid & 127;        // 0..127 (b*16 + c)
    const int t     = threadIdx.x;
    const int tx    = t & 15;           // float4 lane along W
    const int ty    = t >> 4;           // 0..15
    const int warp  = t >> 5;
    const int lane  = t & 31;

    __shared__ float sDpart[8][8];
    __shared__ float sWpart[8][64];
    __shared__ float sSq[8];
    __shared__ float sDfin[8];

    // ---------------- reduce phase: 8 d-slices of this (bc) ----------------
    const float4* base = reinterpret_cast<const float4*>(x)
                       + (size_t)(bc * 64 + chunk * 8) * 1024;

    float dacc[8];
    float hacc[4] = {0.f, 0.f, 0.f, 0.f};
    float4 wacc = make_float4(0.f, 0.f, 0.f, 0.f);
    float sq = 0.f;
    #pragma unroll
    for (int dl = 0; dl < 8; ++dl) dacc[dl] = 0.f;

    #pragma unroll
    for (int dl = 0; dl < 8; ++dl) {
        #pragma unroll
        for (int j = 0; j < 4; ++j) {
            const int h = ty + 16 * j;
            float4 v = base[(dl * 64 + h) * 16 + tx];
            float rs = v.x + v.y + v.z + v.w;
            dacc[dl] += rs;
            hacc[j]  += rs;
            wacc.x += v.x; wacc.y += v.y; wacc.z += v.z; wacc.w += v.w;
            sq += v.x * v.x + v.y * v.y + v.z * v.z + v.w * v.w;
        }
    }

    float* P = &g_part[(size_t)(bc * 8 + chunk) * 144];

    // sumH: half-warp reduce over tx (16 lanes share one ty)
    #pragma unroll
    for (int j = 0; j < 4; ++j) {
        float v = hacc[j];
        #pragma unroll
        for (int m = 8; m >= 1; m >>= 1) v += __shfl_xor_sync(0xffffffffu, v, m);
        if ((lane & 15) == 0) P[8 + ty + 16 * j] = v;
    }
    // sumD: full-warp reduce per dl, cross-warp via smem
    #pragma unroll
    for (int dl = 0; dl < 8; ++dl) {
        float v = dacc[dl];
        #pragma unroll
        for (int m = 16; m >= 1; m >>= 1) v += __shfl_xor_sync(0xffffffffu, v, m);
        if (lane == 0) sDpart[dl][warp] = v;
    }
    // sumW: fold ty-pair within warp, cross-warp via smem
    wacc.x += __shfl_xor_sync(0xffffffffu, wacc.x, 16);
    wacc.y += __shfl_xor_sync(0xffffffffu, wacc.y, 16);
    wacc.z += __shfl_xor_sync(0xffffffffu, wacc.z, 16);
    wacc.w += __shfl_xor_sync(0xffffffffu, wacc.w, 16);
    if (lane < 16) *reinterpret_cast<float4*>(&sWpart[warp][4 * tx]) = wacc;
    // sum(x^2)
    #pragma unroll
    for (int m = 16; m >= 1; m >>= 1) sq += __shfl_xor_sync(0xffffffffu, sq, m);
    if (lane == 0) sSq[warp] = sq;

    __syncthreads();

    if (t < 64) {
        float s = 0.f;
        #pragma unroll
        for (int w = 0; w < 8; ++w) s += sWpart[w][t];
        P[72 + t] = s;
    } else if (t < 72) {
        const int dl = t - 64;
        float s = 0.f;
        #pragma unroll
        for (int w = 0; w < 8; ++w) s += sDpart[dl][w];
        P[dl] = s;
        sDfin[dl] = s;
    } else if (t == 72) {
        float s = 0.f;
        #pragma unroll
        for (int w = 0; w < 8; ++w) s += sSq[w];
        P[136] = s;
    }

    // CTA 0 additionally precomputes c2m[r][h] = mean_s core2[r,h,s]
    if (bid == 0) {
        for (int i = t; i < 2048; i += 256) {
            const float* p = core2 + (size_t)i * 32;
            float s = 0.f;
            #pragma unroll
            for (int k = 0; k < 32; ++k) s += p[k];
            g_c2m[i] = s * (1.f / 32.f);
        }
    }
    __syncthreads();

    if (t == 0) {
        float s = 0.f;
        #pragma unroll
        for (int dl = 0; dl < 8; ++dl) s += sDfin[dl];
        P[137] = s;
        __threadfence();
        atomicAdd(&g_cnt1, 1);
    }
    if (bid < EPI_BASE) return;

    // ---------------- epilogue phase: last 128 CTAs, one per bc ------------
    if (t == 0) {
        while (*(volatile int*)&g_cnt1 < NCTA) __nanosleep(64);
    }
    __syncthreads();
    __threadfence();

    __shared__ float sD[64], sH[64], sW[64];
    __shared__ float sStat[2];   // [0]=scale a, [1]=shift b

    const float* Q0 = g_part + (size_t)bc * 8 * 144;
    if (t < 64) {
        sD[t] = Q0[(t >> 3) * 144 + (t & 7)];   // d slots chunk-disjoint
        float h = 0.f, w = 0.f;
        #pragma unroll
        for (int ch = 0; ch < 8; ++ch) {
            h += Q0[ch * 144 + 8 + t];
            w += Q0[ch * 144 + 72 + t];
        }
        sH[t] = h;
        sW[t] = w;
    }

    const int c = bc & 15;
    if (warp == 3) {
        float S = 0.f, Q = 0.f;
        #pragma unroll
        for (int rep = 0; rep < 2; ++rep) {
            const int p = lane + rep * 32;       // 0..63: (b, chunk) pairs
            const int b = p >> 3, ch = p & 7;
            const float* Pc = g_part + (size_t)((b * 16 + c) * 8 + ch) * 144;
            S += Pc[137];
            Q += Pc[136];
        }
        #pragma unroll
        for (int m = 16; m >= 1; m >>= 1) {
            S += __shfl_xor_sync(0xffffffffu, S, m);
            Q += __shfl_xor_sync(0xffffffffu, Q, m);
        }
        if (lane == 0) {
            const float invN = 1.f / 2097152.f;   // B*D*H*W per channel
            float mean = S * invN;
            float var  = Q * invN - mean * mean;
            float a = rsqrtf(var + 1e-5f) * gamma[c];
            sStat[0] = a;
            sStat[1] = beta[c] - mean * a;
        }
    }
    __syncthreads();

    if (t < 96) {
        const float a  = sStat[0];
        const float b0 = sStat[1];
        const int which = t >> 5;   // 0: m1 (d), 1: m2 (h), 2: m3 (w)
        const int rr    = t & 31;
        const float invHW = 1.f / 4096.f;
        float acc = 0.f;
        if (which == 0) {
            #pragma unroll
            for (int d = 0; d < 64; ++d)
                acc += (a * sD[d] * invHW + b0) * core1[d * 32 + rr];
        } else if (which == 1) {
            #pragma unroll
            for (int h = 0; h < 64; ++h)
                acc += (a * sH[h] * invHW + b0) * g_c2m[rr * 64 + h];
        } else {
            #pragma unroll
            for (int w = 0; w < 64; ++w)
                acc += (a * sW[w] * invHW + b0) * core3[rr * 64 + w];
        }
        // exact GELU (erf form)
        float g = 0.5f * acc * (1.f + erff(acc * 0.70710678118654752f));
        out[bc * 96 + t] = g;
    }
    __syncthreads();

    // self-reset counters for the next graph replay
    if (t == 0) {
        int o = atomicAdd(&g_cnt2, 1);
        if (o == 127) {
            g_cnt1 = 0;
            g_cnt2 = 0;
        }
    }
}

// ---------------------------------------------------------------------------
extern "C" void kernel_launch(void* const* d_in, const int* in_sizes, int n_in,
                              void* d_out, int out_size) {
    const float* x     = (const float*)d_in[0];   // (8,16,64,64,64)
    const float* gamma = (const float*)d_in[1];   // (16)
    const float* beta  = (const float*)d_in[2];   // (16)
    const float* core1 = (const float*)d_in[3];   // (1,64,32)
    const float* core2 = (const float*)d_in[4];   // (32,64,32)
    const float* core3 = (const float*)d_in[5];   // (32,64,1)
    float* out = (float*)d_out;                   // (8, 1536)

    k_fused<<<NCTA, 256>>>(x, gamma, beta, core1, core2, core3, out);
}

// round 4
// speedup vs baseline: 1.0436x; 1.0436x over previous
#include <cuda_runtime.h>
#include <math.h>

// Scratch (device globals — no allocation allowed).
// g_part per (bc, dq): [0:8) sumD(local dl), [8:72) sumH, [72:136) sumW,
// [136] sum(x^2), [137] chunk total. Stride 144 floats.
__device__ float g_part[128 * 8 * 144];
__device__ float g_c2m[32 * 64];

// ---------------------------------------------------------------------------
// Kernel A: streaming reduction. grid (128 bc, 8 dq), block 128.
// Each CTA: 8 d-slices (128 KB contiguous). One wave on 148 SMs.
// ---------------------------------------------------------------------------
__global__ __launch_bounds__(128) void k_reduce(const float* __restrict__ x,
                                                const float* __restrict__ core2) {
    const int bc   = blockIdx.x;    // 0..127 (b*16 + c)
    const int dq   = blockIdx.y;    // 0..7   (d in [dq*8, dq*8+8))
    const int t    = threadIdx.x;
    const int tx   = t & 15;        // float4 lane along W
    const int ty   = t >> 4;        // 0..7
    const int warp = t >> 5;        // 0..3
    const int lane = t & 31;

    __shared__ float sDpart[8][4];
    __shared__ float sWpart[4][64];
    __shared__ float sSq[4];
    __shared__ float sDfin[8];

    const float4* base = reinterpret_cast<const float4*>(x)
                       + (size_t)(bc * 64 + dq * 8) * 1024;   // 1024 float4 per d-slice

    float dacc[8], hacc[8];
    float4 wacc = make_float4(0.f, 0.f, 0.f, 0.f);
    float sq = 0.f;
    #pragma unroll
    for (int i = 0; i < 8; ++i) { dacc[i] = 0.f; hacc[i] = 0.f; }

    // 64 loads/thread: outer dl loop iterates, inner j fully unrolled (8 LDG.128 batched).
    #pragma unroll 2
    for (int dl = 0; dl < 8; ++dl) {
        #pragma unroll
        for (int j = 0; j < 8; ++j) {
            const int h = ty + 8 * j;
            float4 v = base[(dl * 64 + h) * 16 + tx];
            float rs = (v.x + v.y) + (v.z + v.w);
            dacc[dl] += rs;
            hacc[j]  += rs;
            wacc.x += v.x; wacc.y += v.y; wacc.z += v.z; wacc.w += v.w;
            sq = fmaf(v.x, v.x, sq); sq = fmaf(v.y, v.y, sq);
            sq = fmaf(v.z, v.z, sq); sq = fmaf(v.w, v.w, sq);
        }
    }

    float* P = &g_part[(size_t)(bc * 8 + dq) * 144];

    // sumH: reduce over tx within each half-warp (16 lanes share one ty).
    #pragma unroll
    for (int j = 0; j < 8; ++j) {
        float v = hacc[j];
        #pragma unroll
        for (int m = 8; m >= 1; m >>= 1) v += __shfl_xor_sync(0xffffffffu, v, m);
        if ((lane & 15) == 0) P[8 + ty + 8 * j] = v;   // complete sumH for this h
    }
    // sumD: full-warp reduce per dl, cross-warp via smem.
    #pragma unroll
    for (int dl = 0; dl < 8; ++dl) {
        float v = dacc[dl];
        #pragma unroll
        for (int m = 16; m >= 1; m >>= 1) v += __shfl_xor_sync(0xffffffffu, v, m);
        if (lane == 0) sDpart[dl][warp] = v;
    }
    // sumW: fold the warp's two ty values, park per-warp partials in smem.
    wacc.x += __shfl_xor_sync(0xffffffffu, wacc.x, 16);
    wacc.y += __shfl_xor_sync(0xffffffffu, wacc.y, 16);
    wacc.z += __shfl_xor_sync(0xffffffffu, wacc.z, 16);
    wacc.w += __shfl_xor_sync(0xffffffffu, wacc.w, 16);
    if (lane < 16) *reinterpret_cast<float4*>(&sWpart[warp][4 * tx]) = wacc;
    // sum(x^2)
    #pragma unroll
    for (int m = 16; m >= 1; m >>= 1) sq += __shfl_xor_sync(0xffffffffu, sq, m);
    if (lane == 0) sSq[warp] = sq;

    __syncthreads();

    if (t < 64) {
        float s = 0.f;
        #pragma unroll
        for (int w = 0; w < 4; ++w) s += sWpart[w][t];
        P[72 + t] = s;
    } else if (t < 72) {
        const int dl = t - 64;
        float s = 0.f;
        #pragma unroll
        for (int w = 0; w < 4; ++w) s += sDpart[dl][w];
        P[dl] = s;
        sDfin[dl] = s;
    } else if (t == 72) {
        P[136] = sSq[0] + sSq[1] + sSq[2] + sSq[3];
    }
    __syncthreads();
    if (t == 0) {
        float s = 0.f;
        #pragma unroll
        for (int dl = 0; dl < 8; ++dl) s += sDfin[dl];
        P[137] = s;
    }

    // CTA (0,0) precomputes c2m[r][h] = mean_s core2[r,h,s]; overlaps with the
    // memory-bound phase of the other 1023 CTAs. Kernel boundary orders it.
    if (bc == 0 && dq == 0) {
        for (int i = t; i < 2048; i += 128) {
            const float* p = core2 + (size_t)i * 32;
            float s = 0.f;
            #pragma unroll
            for (int k = 0; k < 32; ++k) s += p[k];
            g_c2m[i] = s * (1.f / 32.f);
        }
    }
}

// ---------------------------------------------------------------------------
// Kernel B: channel stats + affine + 3x (64 -> 32) contractions + erf-GELU
// grid: 128 (one per bc)   block: 128
// ---------------------------------------------------------------------------
__global__ __launch_bounds__(128) void k_final(const float* __restrict__ gamma,
                                               const float* __restrict__ beta,
                                               const float* __restrict__ core1,
                                               const float* __restrict__ core3,
                                               float* __restrict__ out) {
    const int bc   = blockIdx.x;
    const int c    = bc & 15;
    const int t    = threadIdx.x;
    const int warp = t >> 5;
    const int lane = t & 31;

    __shared__ float sD[64], sH[64], sW[64];
    __shared__ float sStat[2];   // [0]=scale a, [1]=shift b

    const float* Q0 = g_part + (size_t)bc * 8 * 144;
    if (t < 64) {
        sD[t] = Q0[(t >> 3) * 144 + (t & 7)];   // d slots are dq-disjoint: d == t
        float h = 0.f, w = 0.f;
        #pragma unroll
        for (int ch = 0; ch < 8; ++ch) {
            h += Q0[ch * 144 + 8 + t];
            w += Q0[ch * 144 + 72 + t];
        }
        sH[t] = h;
        sW[t] = w;
    }

    // Channel stats: warp 3 sums the 64 (b, dq) totals for this channel.
    if (warp == 3) {
        float S = 0.f, Q = 0.f;
        #pragma unroll
        for (int rep = 0; rep < 2; ++rep) {
            const int p = lane + rep * 32;       // 0..63
            const int b = p >> 3, ch = p & 7;
            const float* Pc = g_part + (size_t)((b * 16 + c) * 8 + ch) * 144;
            S += Pc[137];
            Q += Pc[136];
        }
        #pragma unroll
        for (int m = 16; m >= 1; m >>= 1) {
            S += __shfl_xor_sync(0xffffffffu, S, m);
            Q += __shfl_xor_sync(0xffffffffu, Q, m);
        }
        if (lane == 0) {
            const float invN = 1.f / 2097152.f;   // B*D*H*W per channel
            float mean = S * invN;
            float var  = Q * invN - mean * mean;
            float a = rsqrtf(var + 1e-5f) * gamma[c];
            sStat[0] = a;
            sStat[1] = beta[c] - mean * a;
        }
    }
    __syncthreads();

    if (t < 96) {
        const float a  = sStat[0];
        const float b0 = sStat[1];
        const int which = t >> 5;   // 0: m1 (d), 1: m2 (h), 2: m3 (w)
        const int rr    = t & 31;
        const float invHW = 1.f / 4096.f;
        float acc = 0.f;
        if (which == 0) {
            #pragma unroll
            for (int d = 0; d < 64; ++d)
                acc += (a * sD[d] * invHW + b0) * core1[d * 32 + rr];
        } else if (which == 1) {
            #pragma unroll
            for (int h = 0; h < 64; ++h)
                acc += (a * sH[h] * invHW + b0) * g_c2m[rr * 64 + h];
        } else {
            #pragma unroll
            for (int w = 0; w < 64; ++w)
                acc += (a * sW[w] * invHW + b0) * core3[rr * 64 + w];
        }
        // exact GELU (erf form, matches torch nn.GELU default)
        float g = 0.5f * acc * (1.f + erff(acc * 0.70710678118654752f));
        out[bc * 96 + t] = g;
    }
}

// ---------------------------------------------------------------------------
extern "C" void kernel_launch(void* const* d_in, const int* in_sizes, int n_in,
                              void* d_out, int out_size) {
    const float* x     = (const float*)d_in[0];   // (8,16,64,64,64)
    const float* gamma = (const float*)d_in[1];   // (16)
    const float* beta  = (const float*)d_in[2];   // (16)
    const float* core1 = (const float*)d_in[3];   // (1,64,32)
    const float* core2 = (const float*)d_in[4];   // (32,64,32)
    const float* core3 = (const float*)d_in[5];   // (32,64,1)
    float* out = (float*)d_out;                   // (8, 1536)

    k_reduce<<<dim3(128, 8), 128>>>(x, core2);
    k_final<<<128, 128>>>(gamma, beta, core1, core3, out);
}

// round 5
// speedup vs baseline: 1.1131x; 1.0667x over previous
#include <cuda_runtime.h>
#include <math.h>

// Scratch (device globals — no allocation allowed).
// g_part per (bc, dq): [0:8) sumD(local dl), [8:72) sumH, [72:136) sumW,
// [136] sum(x^2), [137] chunk total. Stride 144 floats.
__device__ float g_part[128 * 8 * 144];
__device__ float g_c2m[32 * 64];

// ---------------------------------------------------------------------------
// Kernel A: streaming reduction. grid (128 bc, 8 dq) = 1024 CTAs, block 256.
// Each CTA: 8 d-slices (128 KB). 32 fully-unrolled LDG.128 per thread.
// ---------------------------------------------------------------------------
__global__ __launch_bounds__(256) void k_reduce(const float* __restrict__ x,
                                                const float* __restrict__ core2) {
    const int bc   = blockIdx.x;    // 0..127 (b*16 + c)
    const int dq   = blockIdx.y;    // 0..7   (d in [dq*8, dq*8+8))
    const int t    = threadIdx.x;
    const int tx   = t & 15;        // float4 lane along W
    const int ty   = t >> 4;        // 0..15
    const int warp = t >> 5;        // 0..7
    const int lane = t & 31;

    __shared__ float sDpart[8][8];
    __shared__ float sWpart[8][64];
    __shared__ float sSq[8];
    __shared__ float sDfin[8];

    const float4* base = reinterpret_cast<const float4*>(x)
                       + (size_t)(bc * 64 + dq * 8) * 1024;   // 1024 float4 per d-slice

    float dacc[8];
    float hacc[4] = {0.f, 0.f, 0.f, 0.f};
    float4 wacc = make_float4(0.f, 0.f, 0.f, 0.f);
    float sq = 0.f;
    #pragma unroll
    for (int dl = 0; dl < 8; ++dl) dacc[dl] = 0.f;

    // Full unroll: 32 in-flight LDG.128 per thread (proven R2/R3 pattern).
    #pragma unroll
    for (int dl = 0; dl < 8; ++dl) {
        #pragma unroll
        for (int j = 0; j < 4; ++j) {
            const int h = ty + 16 * j;
            float4 v = base[(dl * 64 + h) * 16 + tx];
            float rs = v.x + v.y + v.z + v.w;
            dacc[dl] += rs;
            hacc[j]  += rs;
            wacc.x += v.x; wacc.y += v.y; wacc.z += v.z; wacc.w += v.w;
            sq += v.x * v.x + v.y * v.y + v.z * v.z + v.w * v.w;
        }
    }

    float* P = &g_part[(size_t)(bc * 8 + dq) * 144];

    // sumH: half-warp reduce over tx (16 lanes share one ty)
    #pragma unroll
    for (int j = 0; j < 4; ++j) {
        float v = hacc[j];
        #pragma unroll
        for (int m = 8; m >= 1; m >>= 1) v += __shfl_xor_sync(0xffffffffu, v, m);
        if ((lane & 15) == 0) P[8 + ty + 16 * j] = v;   // complete sumH for this h
    }
    // sumD: full-warp reduce per dl, cross-warp via smem
    #pragma unroll
    for (int dl = 0; dl < 8; ++dl) {
        float v = dacc[dl];
        #pragma unroll
        for (int m = 16; m >= 1; m >>= 1) v += __shfl_xor_sync(0xffffffffu, v, m);
        if (lane == 0) sDpart[dl][warp] = v;
    }
    // sumW: fold ty-pair within warp, cross-warp via smem
    wacc.x += __shfl_xor_sync(0xffffffffu, wacc.x, 16);
    wacc.y += __shfl_xor_sync(0xffffffffu, wacc.y, 16);
    wacc.z += __shfl_xor_sync(0xffffffffu, wacc.z, 16);
    wacc.w += __shfl_xor_sync(0xffffffffu, wacc.w, 16);
    if (lane < 16) *reinterpret_cast<float4*>(&sWpart[warp][4 * tx]) = wacc;
    // sum(x^2)
    #pragma unroll
    for (int m = 16; m >= 1; m >>= 1) sq += __shfl_xor_sync(0xffffffffu, sq, m);
    if (lane == 0) sSq[warp] = sq;

    __syncthreads();

    if (t < 64) {
        float s = 0.f;
        #pragma unroll
        for (int w = 0; w < 8; ++w) s += sWpart[w][t];
        P[72 + t] = s;
    } else if (t < 72) {
        const int dl = t - 64;
        float s = 0.f;
        #pragma unroll
        for (int w = 0; w < 8; ++w) s += sDpart[dl][w];
        P[dl] = s;
        sDfin[dl] = s;
    } else if (t == 72) {
        float s = 0.f;
        #pragma unroll
        for (int w = 0; w < 8; ++w) s += sSq[w];
        P[136] = s;
    }

    // CTA (0,0) precomputes c2m[r][h] = mean_s core2[r,h,s]; overlaps with the
    // memory-bound phase of the other CTAs. Kernel boundary orders it.
    if (bc == 0 && dq == 0) {
        for (int i = t; i < 2048; i += 256) {
            const float* p = core2 + (size_t)i * 32;
            float s = 0.f;
            #pragma unroll
            for (int k = 0; k < 32; ++k) s += p[k];
            g_c2m[i] = s * (1.f / 32.f);
        }
    }
    __syncthreads();

    if (t == 0) {
        float s = 0.f;
        #pragma unroll
        for (int dl = 0; dl < 8; ++dl) s += sDfin[dl];
        P[137] = s;
    }
}

// ---------------------------------------------------------------------------
// Kernel B: channel stats + affine + 3x (64 -> 32) contractions + erf-GELU
// grid: 128 (one per bc)   block: 128
// ---------------------------------------------------------------------------
__global__ __launch_bounds__(128) void k_final(const float* __restrict__ gamma,
                                               const float* __restrict__ beta,
                                               const float* __restrict__ core1,
                                               const float* __restrict__ core3,
                                               float* __restrict__ out) {
    const int bc   = blockIdx.x;
    const int c    = bc & 15;
    const int t    = threadIdx.x;
    const int warp = t >> 5;
    const int lane = t & 31;

    __shared__ float sD[64], sH[64], sW[64];
    __shared__ float sStat[2];   // [0]=scale a, [1]=shift b

    const float* Q0 = g_part + (size_t)bc * 8 * 144;
    if (t < 64) {
        sD[t] = Q0[(t >> 3) * 144 + (t & 7)];   // d slots are dq-disjoint: d == t
        float h = 0.f, w = 0.f;
        #pragma unroll
        for (int ch = 0; ch < 8; ++ch) {
            h += Q0[ch * 144 + 8 + t];
            w += Q0[ch * 144 + 72 + t];
        }
        sH[t] = h;
        sW[t] = w;
    }

    // Channel stats: warp 3 sums the 64 (b, dq) totals for this channel.
    if (warp == 3) {
        float S = 0.f, Q = 0.f;
        #pragma unroll
        for (int rep = 0; rep < 2; ++rep) {
            const int p = lane + rep * 32;       // 0..63
            const int b = p >> 3, ch = p & 7;
            const float* Pc = g_part + (size_t)((b * 16 + c) * 8 + ch) * 144;
            S += Pc[137];
            Q += Pc[136];
        }
        #pragma unroll
        for (int m = 16; m >= 1; m >>= 1) {
            S += __shfl_xor_sync(0xffffffffu, S, m);
            Q += __shfl_xor_sync(0xffffffffu, Q, m);
        }
        if (lane == 0) {
            const float invN = 1.f / 2097152.f;   // B*D*H*W per channel
            float mean = S * invN;
            float var  = Q * invN - mean * mean;
            float a = rsqrtf(var + 1e-5f) * gamma[c];
            sStat[0] = a;
            sStat[1] = beta[c] - mean * a;
        }
    }
    __syncthreads();

    if (t < 96) {
        const float a  = sStat[0];
        const float b0 = sStat[1];
        const int which = t >> 5;   // 0: m1 (d), 1: m2 (h), 2: m3 (w)
        const int rr    = t & 31;
        const float invHW = 1.f / 4096.f;
        float acc = 0.f;
        if (which == 0) {
            #pragma unroll
            for (int d = 0; d < 64; ++d)
                acc += (a * sD[d] * invHW + b0) * core1[d * 32 + rr];
        } else if (which == 1) {
            #pragma unroll
            for (int h = 0; h < 64; ++h)
                acc += (a * sH[h] * invHW + b0) * g_c2m[rr * 64 + h];
        } else {
            #pragma unroll
            for (int w = 0; w < 64; ++w)
                acc += (a * sW[w] * invHW + b0) * core3[rr * 64 + w];
        }
        // exact GELU (erf form, matches torch nn.GELU default)
        float g = 0.5f * acc * (1.f + erff(acc * 0.70710678118654752f));
        out[bc * 96 + t] = g;
    }
}

// ---------------------------------------------------------------------------
extern "C" void kernel_launch(void* const* d_in, const int* in_sizes, int n_in,
                              void* d_out, int out_size) {
    const float* x     = (const float*)d_in[0];   // (8,16,64,64,64)
    const float* gamma = (const float*)d_in[1];   // (16)
    const float* beta  = (const float*)d_in[2];   // (16)
    const float* core1 = (const float*)d_in[3];   // (1,64,32)
    const float* core2 = (const float*)d_in[4];   // (32,64,32)
    const float* core3 = (const float*)d_in[5];   // (32,64,1)
    float* out = (float*)d_out;                   // (8, 1536)

    k_reduce<<<dim3(128, 8), 256>>>(x, core2);
    k_final<<<128, 128>>>(gamma, beta, core1, core3, out);
}